// round 16
// baseline (speedup 1.0000x reference)
#include <cuda_runtime.h>
#include <cuda_bf16.h>
#include <cuda_fp16.h>

#define D 128
#define MAXN 20000
#define MAXE 640000
#define BM 64
#define BK 64

// Scratch (device globals: allocation-free per harness rules).
// Invariant: g_deg is all-zero at kernel_launch entry; scan1 restores this
// every launch (reads then zeroes), so graph replays stay deterministic.
__device__ float4   g_xt4[MAXN * 32];   // fp32 xt (residual path)
__device__ uint2    g_xth[MAXN * 32];   // fp16 mirror of xt (gather path)
__device__ float4   g_buf4[MAXN * 32];
__device__ int      g_deg[MAXN];
__device__ int      g_rowptr[MAXN + 1]; // PARTIAL (per-scan-block); consumers add sbs
__device__ float    g_deginv[MAXN];
__device__ int      g_col[MAXE];
__device__ int      g_rank[MAXE];
__device__ int      g_bsum[32];
__device__ unsigned g_Wh[3][128 * 64];  // W bf16-hi words (2 bf16/word, k-pairs)
__device__ unsigned g_Wl[3][128 * 64];  // W bf16-lo (residual) words

__device__ __forceinline__ int clampi(int v, int n) {
    return (v < 0) ? 0 : (v >= n ? n - 1 : v);
}

// Per-block edge dtype detect: int64 data viewed as int32 has all odd words 0.
__device__ __forceinline__ int detect_is64(const int* __restrict__ w) {
    __shared__ int s64;
    if (threadIdx.x == 0) {
        int acc = 0;
        #pragma unroll
        for (int j = 1; j < 64; j += 2) acc |= w[j];
        s64 = (acc == 0) ? 1 : 0;
    }
    __syncthreads();
    return s64;
}

// Per-block exclusive warp-scan of g_bsum into smem sbs[0..31].
__device__ __forceinline__ void scan_bsum(int* sbs, int nb) {
    if (threadIdx.x < 32) {
        int t = threadIdx.x;
        int v = (t < nb) ? g_bsum[t] : 0;
        int x = v;
        #pragma unroll
        for (int o = 1; o < 32; o <<= 1) {
            int y = __shfl_up_sync(0xffffffffu, x, o);
            if (t >= o) x += y;
        }
        sbs[t] = x - v;
    }
    __syncthreads();
}

// ---------------- CSR build ----------------
// hist: degree histogram; atomicAdd's return value IS the edge's rank within
// its destination bucket -> saved to g_rank, so fill needs no atomic.

__global__ void hist_kernel(const int* __restrict__ w, int E, int Nn) {
    int is64 = detect_is64(w);
    int idx = blockIdx.x * blockDim.x + threadIdx.x;
    int e0 = 2 * idx;
    if (e0 >= E) return;
    int d0, d1 = -1;
    if (is64) {
        const int4* dst4 = (const int4*)(w + 2 * E);
        int4 v = dst4[idx];
        d0 = v.x;
        if (e0 + 1 < E) d1 = v.z;
    } else {
        const int2* dst2 = (const int2*)(w + E);
        int2 v = dst2[idx];
        d0 = v.x;
        if (e0 + 1 < E) d1 = v.y;
    }
    int r0 = atomicAdd(&g_deg[clampi(d0, Nn)], 1);
    if (e0 + 1 < E) {
        int r1 = atomicAdd(&g_deg[clampi(d1, Nn)], 1);
        *(int2*)&g_rank[e0] = make_int2(r0, r1);
    } else {
        g_rank[e0] = r0;
    }
}

// Scan pass: per-block (1024-wide) exclusive scan of degrees -> PARTIAL
// rowptr + per-block sums in g_bsum. Zeroes g_deg (restores invariant).
// Also performs the W fp32->bf16 hi/lo preconversion (fused wconv).

__device__ __forceinline__ unsigned pack_bf16_hi(float2 v, float2& rem) {
    __nv_bfloat16 h0 = __float2bfloat16_rn(v.x);
    __nv_bfloat16 h1 = __float2bfloat16_rn(v.y);
    rem.x = v.x - __bfloat162float(h0);
    rem.y = v.y - __bfloat162float(h1);
    __nv_bfloat162 p = __nv_bfloat162(h0, h1);
    return *reinterpret_cast<unsigned*>(&p);
}
__device__ __forceinline__ unsigned pack_bf16(float2 v) {
    __nv_bfloat162 p = __nv_bfloat162(__float2bfloat16_rn(v.x), __float2bfloat16_rn(v.y));
    return *reinterpret_cast<unsigned*>(&p);
}

__global__ __launch_bounds__(1024) void scan1_kernel(
    int Nn, const float* __restrict__ W1, const float* __restrict__ W2,
    const float* __restrict__ W3)
{
    // Fused W conversion: 3*8192 = 24576 words over the whole grid.
    int gtid = blockIdx.x * 1024 + threadIdx.x;
    int gsz = gridDim.x * 1024;
    for (int idx = gtid; idx < 3 * 8192; idx += gsz) {
        int l = idx >> 13;
        int t = idx & 8191;
        const float* W = (l == 0) ? W1 : (l == 1) ? W2 : W3;
        float2 v = *(const float2*)&W[2 * t];
        float2 rem;
        g_Wh[l][t] = pack_bf16_hi(v, rem);
        g_Wl[l][t] = pack_bf16(rem);
    }

    __shared__ int wsum[32];
    int i = gtid;
    int lane = threadIdx.x & 31;
    int wrp = threadIdx.x >> 5;
    int v = 0;
    if (i < Nn) {
        v = g_deg[i];
        g_deg[i] = 0;
    }
    int x = v;
    #pragma unroll
    for (int o = 1; o < 32; o <<= 1) {
        int y = __shfl_up_sync(0xffffffffu, x, o);
        if (lane >= o) x += y;
    }
    if (lane == 31) wsum[wrp] = x;
    __syncthreads();
    if (threadIdx.x < 32) {
        int y = wsum[threadIdx.x];
        int z = y;
        #pragma unroll
        for (int o = 1; o < 32; o <<= 1) {
            int t = __shfl_up_sync(0xffffffffu, z, o);
            if (threadIdx.x >= o) z += t;
        }
        wsum[threadIdx.x] = z - y;
    }
    __syncthreads();
    int excl = x - v + wsum[wrp];
    if (i < Nn) {
        g_rowptr[i] = excl;
        g_deginv[i] = (v > 0) ? 1.0f / (float)v : 0.0f;
        if (i == Nn - 1) g_rowptr[Nn] = excl + v;   // partial; same sbs block
    }
    if (threadIdx.x == 1023) g_bsum[blockIdx.x] = excl + v;
}

// fill: no atomics — position = rowptr_partial[dst] + sbs[dst>>10] + rank[e].
__global__ void fill_kernel(const int* __restrict__ w, int E, int Nn, int nb) {
    int is64 = detect_is64(w);
    __shared__ int sbs[32];
    scan_bsum(sbs, nb);
    int idx = blockIdx.x * blockDim.x + threadIdx.x;
    int e0 = 2 * idx;
    if (e0 >= E) return;
    int s0, d0, s1 = 0, d1 = 0;
    bool two = (e0 + 1 < E);
    if (is64) {
        const int4* src4 = (const int4*)w;
        const int4* dst4 = (const int4*)(w + 2 * E);
        int4 sv = src4[idx];
        int4 dv = dst4[idx];
        s0 = sv.x; d0 = dv.x; s1 = sv.z; d1 = dv.z;
    } else {
        const int2* src2 = (const int2*)w;
        const int2* dst2 = (const int2*)(w + E);
        int2 sv = src2[idx];
        int2 dv = dst2[idx];
        s0 = sv.x; d0 = dv.x; s1 = sv.y; d1 = dv.y;
    }
    d0 = clampi(d0, Nn);
    if (two) {
        d1 = clampi(d1, Nn);
        int2 rk = *(const int2*)&g_rank[e0];
        g_col[g_rowptr[d0] + sbs[d0 >> 10] + rk.x] = clampi(s0, Nn);
        g_col[g_rowptr[d1] + sbs[d1 >> 10] + rk.y] = clampi(s1, Nn);
    } else {
        g_col[g_rowptr[d0] + sbs[d0 >> 10] + g_rank[e0]] = clampi(s0, Nn);
    }
}

// ---------------- GEMM: g_xt4/g_xth = Xin @ W^T + b ----------------
// Tensor-core mma.sync m16n8k16 bf16, hi/lo split: y = Ah*Bh + Ah*Bl + Al*Bh.
// W already bf16 hi/lo in global (g_Wh/g_Wl), loaded straight to SMEM.
// __launch_bounds__(256, 2): cap regs at 128 so 2 CTAs/SM co-reside
// (48KB SMEM x2 = 96KB < 228KB) — R14 showed regs=255/occ=12.5% made this
// kernel latency-bound at 23us/launch.

__device__ __forceinline__ void mma_bf16(
    float* c, unsigned a0, unsigned a1, unsigned a2, unsigned a3,
    unsigned b0, unsigned b1)
{
    asm volatile(
        "mma.sync.aligned.m16n8k16.row.col.f32.bf16.bf16.f32 "
        "{%0,%1,%2,%3}, {%4,%5,%6,%7}, {%8,%9}, {%0,%1,%2,%3};"
        : "+f"(c[0]), "+f"(c[1]), "+f"(c[2]), "+f"(c[3])
        : "r"(a0), "r"(a1), "r"(a2), "r"(a3), "r"(b0), "r"(b1));
}

__device__ __forceinline__ int swz(int r, int w) { return r * 32 + (w ^ ((r & 7) << 2)); }

__global__ __launch_bounds__(256, 2) void gemm_kernel(
    const float* __restrict__ Xin, int layer,
    const float* __restrict__ b, int Nn)
{
    const float* X = Xin ? Xin : (const float*)g_buf4;
    const unsigned* gWh = g_Wh[layer];
    const unsigned* gWl = g_Wl[layer];
    __shared__ unsigned sAh[64 * 32];
    __shared__ unsigned sAl[64 * 32];
    __shared__ unsigned sWh[128 * 32];
    __shared__ unsigned sWl[128 * 32];

    int tid = threadIdx.x;
    int lane = tid & 31;
    int wrp = tid >> 5;
    int wm = wrp & 3;
    int wn = wrp >> 2;
    int g = lane >> 2;
    int tq = lane & 3;
    int row0 = blockIdx.x * BM;

    float c[8][4];
    #pragma unroll
    for (int j = 0; j < 8; j++)
        #pragma unroll
        for (int q = 0; q < 4; q++) c[j][q] = 0.f;

    for (int kt = 0; kt < D; kt += BK) {
        int ktw = kt >> 1;
        if (kt) __syncthreads();
        #pragma unroll
        for (int i = 0; i < 8; i++) {
            int idx = tid + i * 256;
            int r = idx >> 5, w = idx & 31;
            int gr = row0 + r;
            float2 v = (gr < Nn) ? *(const float2*)&X[gr * D + kt + 2 * w]
                                 : make_float2(0.f, 0.f);
            float2 rem;
            sAh[swz(r, w)] = pack_bf16_hi(v, rem);
            sAl[swz(r, w)] = pack_bf16(rem);
        }
        #pragma unroll
        for (int i = 0; i < 8; i++) {
            int idx = tid + i * 256;
            int r = idx >> 4;
            int w2 = (idx & 15) << 1;
            int gwi = r * 64 + ktw + w2;
            uint2 vh = *(const uint2*)&gWh[gwi];
            uint2 vl = *(const uint2*)&gWl[gwi];
            *(uint2*)&sWh[swz(r, w2)] = vh;
            *(uint2*)&sWl[swz(r, w2)] = vl;
        }
        __syncthreads();

        #pragma unroll
        for (int ks = 0; ks < 4; ks++) {
            int ra = wm * 16 + g;
            int wa = ks * 8 + tq;
            unsigned ah0 = sAh[swz(ra, wa)];
            unsigned ah1 = sAh[swz(ra + 8, wa)];
            unsigned ah2 = sAh[swz(ra, wa + 4)];
            unsigned ah3 = sAh[swz(ra + 8, wa + 4)];
            unsigned al0 = sAl[swz(ra, wa)];
            unsigned al1 = sAl[swz(ra + 8, wa)];
            unsigned al2 = sAl[swz(ra, wa + 4)];
            unsigned al3 = sAl[swz(ra + 8, wa + 4)];
            #pragma unroll 4
            for (int j = 0; j < 8; j++) {
                int rb = wn * 64 + j * 8 + g;
                unsigned bh0 = sWh[swz(rb, wa)];
                unsigned bh1 = sWh[swz(rb, wa + 4)];
                unsigned bl0 = sWl[swz(rb, wa)];
                unsigned bl1 = sWl[swz(rb, wa + 4)];
                mma_bf16(c[j], ah0, ah1, ah2, ah3, bh0, bh1);
                mma_bf16(c[j], ah0, ah1, ah2, ah3, bl0, bl1);
                mma_bf16(c[j], al0, al1, al2, al3, bh0, bh1);
            }
        }
    }

    float* xtf = (float*)g_xt4;
    __half2* xth2 = (__half2*)g_xth;
    int r0a = row0 + wm * 16 + g;
    #pragma unroll
    for (int j = 0; j < 8; j++) {
        int cn = wn * 64 + j * 8 + 2 * tq;
        float bx = b[cn], by = b[cn + 1];
        float2 lo = make_float2(c[j][0] + bx, c[j][1] + by);
        float2 hi = make_float2(c[j][2] + bx, c[j][3] + by);
        if (r0a < Nn) {
            *(float2*)&xtf[r0a * D + cn] = lo;
            xth2[r0a * 64 + cn / 2] = __floats2half2_rn(lo.x, lo.y);
        }
        if (r0a + 8 < Nn) {
            *(float2*)&xtf[(r0a + 8) * D + cn] = hi;
            xth2[(r0a + 8) * 64 + cn / 2] = __floats2half2_rn(hi.x, hi.y);
        }
    }
}

// ---------------- Aggregation: out = relu(mean_in(xt[src])) + xt ----------------
// Gather fp16 mirror; fp16 pair-accumulate (HADD2), fp32 flush every 8 edges.
// rowptr finalized on the fly via sbs. Warp per node.

__device__ __forceinline__ void acc_half4(float4& acc, uint2 p) {
    __half2 h01 = *reinterpret_cast<__half2*>(&p.x);
    __half2 h23 = *reinterpret_cast<__half2*>(&p.y);
    float2 f01 = __half22float2(h01);
    float2 f23 = __half22float2(h23);
    acc.x += f01.x; acc.y += f01.y; acc.z += f23.x; acc.w += f23.y;
}

__global__ __launch_bounds__(256) void agg_kernel(float4* __restrict__ Oout, int Nn, int nb)
{
    __shared__ int sbs[32];
    scan_bsum(sbs, nb);
    int gw = (blockIdx.x * blockDim.x + threadIdx.x) >> 5;
    int lane = threadIdx.x & 31;
    if (gw >= Nn) return;
    float4* out = Oout ? Oout : g_buf4;
    int s = g_rowptr[gw] + sbs[gw >> 10];
    int e = g_rowptr[gw + 1] + sbs[(gw + 1) >> 10];
    float4 acc = make_float4(0.f, 0.f, 0.f, 0.f);
    int i = s;
    for (; i + 8 <= e; i += 8) {
        uint2 p[8];
        #pragma unroll
        for (int u = 0; u < 8; u++) p[u] = g_xth[g_col[i + u] * 32 + lane];
        __half2 h01 = __float2half2_rn(0.f);
        __half2 h23 = __float2half2_rn(0.f);
        #pragma unroll
        for (int u = 0; u < 8; u++) {
            h01 = __hadd2(h01, *reinterpret_cast<__half2*>(&p[u].x));
            h23 = __hadd2(h23, *reinterpret_cast<__half2*>(&p[u].y));
        }
        float2 f01 = __half22float2(h01);
        float2 f23 = __half22float2(h23);
        acc.x += f01.x; acc.y += f01.y; acc.z += f23.x; acc.w += f23.y;
    }
    for (; i < e; i++) {
        uint2 p = g_xth[g_col[i] * 32 + lane];
        acc_half4(acc, p);
    }
    float di = g_deginv[gw];
    float4 xv = g_xt4[gw * 32 + lane];
    float4 o;
    o.x = fmaxf(acc.x * di, 0.f) + xv.x;
    o.y = fmaxf(acc.y * di, 0.f) + xv.y;
    o.z = fmaxf(acc.z * di, 0.f) + xv.z;
    o.w = fmaxf(acc.w * di, 0.f) + xv.w;
    out[gw * 32 + lane] = o;
}

// ---------------- launch ----------------

extern "C" void kernel_launch(void* const* d_in, const int* in_sizes, int n_in,
                              void* d_out, int out_size)
{
    const float* x  = (const float*)d_in[0];
    const int*   ew = (const int*)d_in[1];     // edge_index words (int32 view)
    const float* W1 = (const float*)d_in[2];
    const float* b1 = (const float*)d_in[3];
    const float* W2 = (const float*)d_in[4];
    const float* b2 = (const float*)d_in[5];
    const float* W3 = (const float*)d_in[6];
    const float* b3 = (const float*)d_in[7];
    float4* out = (float4*)d_out;

    int Nn = in_sizes[0] / D;       // 20000
    int E  = in_sizes[1] / 2;       // 640000

    int gb_e2 = ((E + 1) / 2 + 255) / 256;
    int gb_gemm = (Nn + BM - 1) / BM;
    int gb_agg = (Nn * 32 + 255) / 256;
    int nb_scan = (Nn + 1023) / 1024;

    hist_kernel<<<gb_e2, 256>>>(ew, E, Nn);
    scan1_kernel<<<nb_scan, 1024>>>(Nn, W1, W2, W3);
    fill_kernel<<<gb_e2, 256>>>(ew, E, Nn, nb_scan);

    // layer 1: x -> xt -> g_buf4
    gemm_kernel<<<gb_gemm, 256>>>(x, 0, b1, Nn);
    agg_kernel<<<gb_agg, 256>>>(nullptr, Nn, nb_scan);
    // layer 2: g_buf4 -> xt -> g_buf4
    gemm_kernel<<<gb_gemm, 256>>>(nullptr, 1, b2, Nn);
    agg_kernel<<<gb_agg, 256>>>(nullptr, Nn, nb_scan);
    // layer 3: g_buf4 -> xt -> out
    gemm_kernel<<<gb_gemm, 256>>>(nullptr, 2, b3, Nn);
    agg_kernel<<<gb_agg, 256>>>(out, Nn, nb_scan);
}

// round 17
// speedup vs baseline: 1.2398x; 1.2398x over previous
#include <cuda_runtime.h>
#include <cuda_bf16.h>
#include <cuda_fp16.h>

#define D 128
#define MAXN 20000
#define MAXE 640000
#define BM 64
#define BK 64

// Scratch (device globals: allocation-free per harness rules).
// Invariant: g_deg is all-zero at kernel_launch entry; scan1 restores this
// every launch (reads then zeroes), so graph replays stay deterministic.
__device__ float4   g_xt4[MAXN * 32];   // fp32 xt (residual path)
__device__ uint2    g_xth[MAXN * 32];   // fp16 mirror of xt (gather path)
__device__ float4   g_buf4[MAXN * 32];
__device__ int      g_deg[MAXN];
__device__ int      g_rowptr[MAXN + 1]; // PARTIAL (per-scan-block); consumers add sbs
__device__ float    g_deginv[MAXN];
__device__ int      g_col[MAXE];
__device__ int      g_rank[MAXE];
__device__ int      g_bsum[32];
__device__ unsigned g_Wh[3][128 * 64];  // W bf16-hi words (2 bf16/word, k-pairs)
__device__ unsigned g_Wl[3][128 * 64];  // W bf16-lo (residual) words

__device__ __forceinline__ int clampi(int v, int n) {
    return (v < 0) ? 0 : (v >= n ? n - 1 : v);
}

// Per-block edge dtype detect: int64 data viewed as int32 has all odd words 0.
__device__ __forceinline__ int detect_is64(const int* __restrict__ w) {
    __shared__ int s64;
    if (threadIdx.x == 0) {
        int acc = 0;
        #pragma unroll
        for (int j = 1; j < 64; j += 2) acc |= w[j];
        s64 = (acc == 0) ? 1 : 0;
    }
    __syncthreads();
    return s64;
}

// Per-block exclusive warp-scan of g_bsum into smem sbs[0..31].
__device__ __forceinline__ void scan_bsum(int* sbs, int nb) {
    if (threadIdx.x < 32) {
        int t = threadIdx.x;
        int v = (t < nb) ? g_bsum[t] : 0;
        int x = v;
        #pragma unroll
        for (int o = 1; o < 32; o <<= 1) {
            int y = __shfl_up_sync(0xffffffffu, x, o);
            if (t >= o) x += y;
        }
        sbs[t] = x - v;
    }
    __syncthreads();
}

// ---------------- CSR build ----------------
// hist: degree histogram; atomicAdd's return value IS the edge's rank within
// its destination bucket -> saved to g_rank, so fill needs no atomic.

__global__ void hist_kernel(const int* __restrict__ w, int E, int Nn) {
    int is64 = detect_is64(w);
    int idx = blockIdx.x * blockDim.x + threadIdx.x;
    int e0 = 2 * idx;
    if (e0 >= E) return;
    int d0, d1 = -1;
    if (is64) {
        const int4* dst4 = (const int4*)(w + 2 * E);
        int4 v = dst4[idx];
        d0 = v.x;
        if (e0 + 1 < E) d1 = v.z;
    } else {
        const int2* dst2 = (const int2*)(w + E);
        int2 v = dst2[idx];
        d0 = v.x;
        if (e0 + 1 < E) d1 = v.y;
    }
    int r0 = atomicAdd(&g_deg[clampi(d0, Nn)], 1);
    if (e0 + 1 < E) {
        int r1 = atomicAdd(&g_deg[clampi(d1, Nn)], 1);
        *(int2*)&g_rank[e0] = make_int2(r0, r1);
    } else {
        g_rank[e0] = r0;
    }
}

// Scan pass: per-block (1024-wide) exclusive scan of degrees -> PARTIAL
// rowptr + per-block sums in g_bsum. Zeroes g_deg (restores invariant).
// Also performs the W fp32->bf16 hi/lo preconversion (fused wconv).

__device__ __forceinline__ unsigned pack_bf16_hi(float2 v, float2& rem) {
    __nv_bfloat16 h0 = __float2bfloat16_rn(v.x);
    __nv_bfloat16 h1 = __float2bfloat16_rn(v.y);
    rem.x = v.x - __bfloat162float(h0);
    rem.y = v.y - __bfloat162float(h1);
    __nv_bfloat162 p = __nv_bfloat162(h0, h1);
    return *reinterpret_cast<unsigned*>(&p);
}
__device__ __forceinline__ unsigned pack_bf16(float2 v) {
    __nv_bfloat162 p = __nv_bfloat162(__float2bfloat16_rn(v.x), __float2bfloat16_rn(v.y));
    return *reinterpret_cast<unsigned*>(&p);
}

__global__ __launch_bounds__(1024) void scan1_kernel(
    int Nn, const float* __restrict__ W1, const float* __restrict__ W2,
    const float* __restrict__ W3)
{
    // Fused W conversion: 3*8192 = 24576 words over the whole grid.
    int gtid = blockIdx.x * 1024 + threadIdx.x;
    int gsz = gridDim.x * 1024;
    for (int idx = gtid; idx < 3 * 8192; idx += gsz) {
        int l = idx >> 13;
        int t = idx & 8191;
        const float* W = (l == 0) ? W1 : (l == 1) ? W2 : W3;
        float2 v = *(const float2*)&W[2 * t];
        float2 rem;
        g_Wh[l][t] = pack_bf16_hi(v, rem);
        g_Wl[l][t] = pack_bf16(rem);
    }

    __shared__ int wsum[32];
    int i = gtid;
    int lane = threadIdx.x & 31;
    int wrp = threadIdx.x >> 5;
    int v = 0;
    if (i < Nn) {
        v = g_deg[i];
        g_deg[i] = 0;
    }
    int x = v;
    #pragma unroll
    for (int o = 1; o < 32; o <<= 1) {
        int y = __shfl_up_sync(0xffffffffu, x, o);
        if (lane >= o) x += y;
    }
    if (lane == 31) wsum[wrp] = x;
    __syncthreads();
    if (threadIdx.x < 32) {
        int y = wsum[threadIdx.x];
        int z = y;
        #pragma unroll
        for (int o = 1; o < 32; o <<= 1) {
            int t = __shfl_up_sync(0xffffffffu, z, o);
            if (threadIdx.x >= o) z += t;
        }
        wsum[threadIdx.x] = z - y;
    }
    __syncthreads();
    int excl = x - v + wsum[wrp];
    if (i < Nn) {
        g_rowptr[i] = excl;
        g_deginv[i] = (v > 0) ? 1.0f / (float)v : 0.0f;
        if (i == Nn - 1) g_rowptr[Nn] = excl + v;   // partial; same sbs block
    }
    if (threadIdx.x == 1023) g_bsum[blockIdx.x] = excl + v;
}

// fill: no atomics — position = rowptr_partial[dst] + sbs[dst>>10] + rank[e].
__global__ void fill_kernel(const int* __restrict__ w, int E, int Nn, int nb) {
    int is64 = detect_is64(w);
    __shared__ int sbs[32];
    scan_bsum(sbs, nb);
    int idx = blockIdx.x * blockDim.x + threadIdx.x;
    int e0 = 2 * idx;
    if (e0 >= E) return;
    int s0, d0, s1 = 0, d1 = 0;
    bool two = (e0 + 1 < E);
    if (is64) {
        const int4* src4 = (const int4*)w;
        const int4* dst4 = (const int4*)(w + 2 * E);
        int4 sv = src4[idx];
        int4 dv = dst4[idx];
        s0 = sv.x; d0 = dv.x; s1 = sv.z; d1 = dv.z;
    } else {
        const int2* src2 = (const int2*)w;
        const int2* dst2 = (const int2*)(w + E);
        int2 sv = src2[idx];
        int2 dv = dst2[idx];
        s0 = sv.x; d0 = dv.x; s1 = sv.y; d1 = dv.y;
    }
    d0 = clampi(d0, Nn);
    if (two) {
        d1 = clampi(d1, Nn);
        int2 rk = *(const int2*)&g_rank[e0];
        g_col[g_rowptr[d0] + sbs[d0 >> 10] + rk.x] = clampi(s0, Nn);
        g_col[g_rowptr[d1] + sbs[d1 >> 10] + rk.y] = clampi(s1, Nn);
    } else {
        g_col[g_rowptr[d0] + sbs[d0 >> 10] + g_rank[e0]] = clampi(s0, Nn);
    }
}

// ---------------- GEMM: g_xt4/g_xth = Xin @ W^T + b ----------------
// Tensor-core mma.sync m16n8k16 bf16, hi/lo split: y = Ah*Bh + Ah*Bl + Al*Bh.
// 512 threads / 16 warps per CTA; each warp owns a 16x32 tile (16 accums) —
// small register footprint (no launch_bounds cap, no spills) and 16 warps/SM
// for latency hiding. R16 lesson: capping regs spills; shrink the tile instead.

__device__ __forceinline__ void mma_bf16(
    float* c, unsigned a0, unsigned a1, unsigned a2, unsigned a3,
    unsigned b0, unsigned b1)
{
    asm volatile(
        "mma.sync.aligned.m16n8k16.row.col.f32.bf16.bf16.f32 "
        "{%0,%1,%2,%3}, {%4,%5,%6,%7}, {%8,%9}, {%0,%1,%2,%3};"
        : "+f"(c[0]), "+f"(c[1]), "+f"(c[2]), "+f"(c[3])
        : "r"(a0), "r"(a1), "r"(a2), "r"(a3), "r"(b0), "r"(b1));
}

__device__ __forceinline__ int swz(int r, int w) { return r * 32 + (w ^ ((r & 7) << 2)); }

__global__ __launch_bounds__(512) void gemm_kernel(
    const float* __restrict__ Xin, int layer,
    const float* __restrict__ b, int Nn)
{
    const float* X = Xin ? Xin : (const float*)g_buf4;
    const unsigned* gWh = g_Wh[layer];
    const unsigned* gWl = g_Wl[layer];
    __shared__ unsigned sAh[64 * 32];
    __shared__ unsigned sAl[64 * 32];
    __shared__ unsigned sWh[128 * 32];
    __shared__ unsigned sWl[128 * 32];

    int tid = threadIdx.x;
    int lane = tid & 31;
    int wrp = tid >> 5;               // 0..15
    int wm = wrp & 3;                 // rows wm*16 .. +15
    int wn = wrp >> 2;                // cols wn*32 .. +31
    int g = lane >> 2;                // 0..7
    int tq = lane & 3;                // 0..3
    int row0 = blockIdx.x * BM;

    float c[4][4];
    #pragma unroll
    for (int j = 0; j < 4; j++)
        #pragma unroll
        for (int q = 0; q < 4; q++) c[j][q] = 0.f;

    for (int kt = 0; kt < D; kt += BK) {
        int ktw = kt >> 1;
        if (kt) __syncthreads();
        // X tile: 64 rows x 32 words = 2048 words over 512 threads
        #pragma unroll
        for (int i = 0; i < 4; i++) {
            int idx = tid + i * 512;
            int r = idx >> 5, w = idx & 31;
            int gr = row0 + r;
            float2 v = (gr < Nn) ? *(const float2*)&X[gr * D + kt + 2 * w]
                                 : make_float2(0.f, 0.f);
            float2 rem;
            sAh[swz(r, w)] = pack_bf16_hi(v, rem);
            sAl[swz(r, w)] = pack_bf16(rem);
        }
        // W tile: 128 rows x 32 words, uint2 copies (2048 uint2 over 512 thr)
        #pragma unroll
        for (int i = 0; i < 4; i++) {
            int idx = tid + i * 512;
            int r = idx >> 4;
            int w2 = (idx & 15) << 1;
            int gwi = r * 64 + ktw + w2;
            uint2 vh = *(const uint2*)&gWh[gwi];
            uint2 vl = *(const uint2*)&gWl[gwi];
            *(uint2*)&sWh[swz(r, w2)] = vh;
            *(uint2*)&sWl[swz(r, w2)] = vl;
        }
        __syncthreads();

        #pragma unroll
        for (int ks = 0; ks < 4; ks++) {
            int ra = wm * 16 + g;
            int wa = ks * 8 + tq;
            unsigned ah0 = sAh[swz(ra, wa)];
            unsigned ah1 = sAh[swz(ra + 8, wa)];
            unsigned ah2 = sAh[swz(ra, wa + 4)];
            unsigned ah3 = sAh[swz(ra + 8, wa + 4)];
            unsigned al0 = sAl[swz(ra, wa)];
            unsigned al1 = sAl[swz(ra + 8, wa)];
            unsigned al2 = sAl[swz(ra, wa + 4)];
            unsigned al3 = sAl[swz(ra + 8, wa + 4)];
            #pragma unroll
            for (int j = 0; j < 4; j++) {
                int rb = wn * 32 + j * 8 + g;
                unsigned bh0 = sWh[swz(rb, wa)];
                unsigned bh1 = sWh[swz(rb, wa + 4)];
                unsigned bl0 = sWl[swz(rb, wa)];
                unsigned bl1 = sWl[swz(rb, wa + 4)];
                mma_bf16(c[j], ah0, ah1, ah2, ah3, bh0, bh1);
                mma_bf16(c[j], ah0, ah1, ah2, ah3, bl0, bl1);
                mma_bf16(c[j], al0, al1, al2, al3, bh0, bh1);
            }
        }
    }

    float* xtf = (float*)g_xt4;
    __half2* xth2 = (__half2*)g_xth;
    int r0a = row0 + wm * 16 + g;
    #pragma unroll
    for (int j = 0; j < 4; j++) {
        int cn = wn * 32 + j * 8 + 2 * tq;
        float bx = b[cn], by = b[cn + 1];
        float2 lo = make_float2(c[j][0] + bx, c[j][1] + by);
        float2 hi = make_float2(c[j][2] + bx, c[j][3] + by);
        if (r0a < Nn) {
            *(float2*)&xtf[r0a * D + cn] = lo;
            xth2[r0a * 64 + cn / 2] = __floats2half2_rn(lo.x, lo.y);
        }
        if (r0a + 8 < Nn) {
            *(float2*)&xtf[(r0a + 8) * D + cn] = hi;
            xth2[(r0a + 8) * 64 + cn / 2] = __floats2half2_rn(hi.x, hi.y);
        }
    }
}

// ---------------- Aggregation: out = relu(mean_in(xt[src])) + xt ----------------
// Gather fp16 mirror; fp16 pair-accumulate (HADD2), fp32 flush every 8 edges.
// rowptr finalized on the fly via sbs. Warp per node.

__device__ __forceinline__ void acc_half4(float4& acc, uint2 p) {
    __half2 h01 = *reinterpret_cast<__half2*>(&p.x);
    __half2 h23 = *reinterpret_cast<__half2*>(&p.y);
    float2 f01 = __half22float2(h01);
    float2 f23 = __half22float2(h23);
    acc.x += f01.x; acc.y += f01.y; acc.z += f23.x; acc.w += f23.y;
}

__global__ __launch_bounds__(256) void agg_kernel(float4* __restrict__ Oout, int Nn, int nb)
{
    __shared__ int sbs[32];
    scan_bsum(sbs, nb);
    int gw = (blockIdx.x * blockDim.x + threadIdx.x) >> 5;
    int lane = threadIdx.x & 31;
    if (gw >= Nn) return;
    float4* out = Oout ? Oout : g_buf4;
    int s = g_rowptr[gw] + sbs[gw >> 10];
    int e = g_rowptr[gw + 1] + sbs[(gw + 1) >> 10];
    float4 acc = make_float4(0.f, 0.f, 0.f, 0.f);
    int i = s;
    for (; i + 8 <= e; i += 8) {
        uint2 p[8];
        #pragma unroll
        for (int u = 0; u < 8; u++) p[u] = g_xth[g_col[i + u] * 32 + lane];
        __half2 h01 = __float2half2_rn(0.f);
        __half2 h23 = __float2half2_rn(0.f);
        #pragma unroll
        for (int u = 0; u < 8; u++) {
            h01 = __hadd2(h01, *reinterpret_cast<__half2*>(&p[u].x));
            h23 = __hadd2(h23, *reinterpret_cast<__half2*>(&p[u].y));
        }
        float2 f01 = __half22float2(h01);
        float2 f23 = __half22float2(h23);
        acc.x += f01.x; acc.y += f01.y; acc.z += f23.x; acc.w += f23.y;
    }
    for (; i < e; i++) {
        uint2 p = g_xth[g_col[i] * 32 + lane];
        acc_half4(acc, p);
    }
    float di = g_deginv[gw];
    float4 xv = g_xt4[gw * 32 + lane];
    float4 o;
    o.x = fmaxf(acc.x * di, 0.f) + xv.x;
    o.y = fmaxf(acc.y * di, 0.f) + xv.y;
    o.z = fmaxf(acc.z * di, 0.f) + xv.z;
    o.w = fmaxf(acc.w * di, 0.f) + xv.w;
    out[gw * 32 + lane] = o;
}

// ---------------- launch ----------------

extern "C" void kernel_launch(void* const* d_in, const int* in_sizes, int n_in,
                              void* d_out, int out_size)
{
    const float* x  = (const float*)d_in[0];
    const int*   ew = (const int*)d_in[1];     // edge_index words (int32 view)
    const float* W1 = (const float*)d_in[2];
    const float* b1 = (const float*)d_in[3];
    const float* W2 = (const float*)d_in[4];
    const float* b2 = (const float*)d_in[5];
    const float* W3 = (const float*)d_in[6];
    const float* b3 = (const float*)d_in[7];
    float4* out = (float4*)d_out;

    int Nn = in_sizes[0] / D;       // 20000
    int E  = in_sizes[1] / 2;       // 640000

    int gb_e2 = ((E + 1) / 2 + 255) / 256;
    int gb_gemm = (Nn + BM - 1) / BM;
    int gb_agg = (Nn * 32 + 255) / 256;
    int nb_scan = (Nn + 1023) / 1024;

    hist_kernel<<<gb_e2, 256>>>(ew, E, Nn);
    scan1_kernel<<<nb_scan, 1024>>>(Nn, W1, W2, W3);
    fill_kernel<<<gb_e2, 256>>>(ew, E, Nn, nb_scan);

    // layer 1: x -> xt -> g_buf4
    gemm_kernel<<<gb_gemm, 512>>>(x, 0, b1, Nn);
    agg_kernel<<<gb_agg, 256>>>(nullptr, Nn, nb_scan);
    // layer 2: g_buf4 -> xt -> g_buf4
    gemm_kernel<<<gb_gemm, 512>>>(nullptr, 1, b2, Nn);
    agg_kernel<<<gb_agg, 256>>>(nullptr, Nn, nb_scan);
    // layer 3: g_buf4 -> xt -> out
    gemm_kernel<<<gb_gemm, 512>>>(nullptr, 2, b3, Nn);
    agg_kernel<<<gb_agg, 256>>>(out, Nn, nb_scan);
}